// round 7
// baseline (speedup 1.0000x reference)
#include <cuda_runtime.h>
#include <math.h>
#include <stdint.h>

// StableMoEGate v4: FFMA2 GEMM, 8x4 micro-tile, split-K(2), 256 thr, 2 CTA/SM.
// logits = x @ W^T (T=16384, H=4096, E=64); softmax; top-2; renorm softmax.
// Output: single f32 buffer [2T scores][2T idx-as-float][1 aux=0].
//
// CTA: 256 thr (8 warps) = (K-group 0|1) x (expert quarter 0..3).
// Warp: 8 tok-lanes x 4 exp-lanes, 8x4 f32x2-accs -> 64 tok x 16 exp.
// smem: 4 buffers (double x 2 K-groups) of [x 64x32k | w 64x32k] = 16KB each.

#define Hdim  4096
#define Edim  64
#define MT    64
#define KT    32
#define ITERS 64            // per K-group: 2048/32
#define BUFB  16384
#define SMEM_BYTES 65536

static __device__ __forceinline__ uint32_t smem_u32(const void* p) {
    uint32_t a;
    asm("{ .reg .u64 t; cvta.to.shared.u64 t, %1; cvt.u32.u64 %0, t; }" : "=r"(a) : "l"(p));
    return a;
}

__global__ void __launch_bounds__(256, 2) moe_gate_v4_kernel(
    const float* __restrict__ x,
    const float* __restrict__ W,
    float* __restrict__ out,
    int T)
{
    extern __shared__ float smem[];
    const uint32_t sbase = smem_u32(smem);

    const int tid = threadIdx.x;
    const int wid = tid >> 5;
    const int lid = tid & 31;
    const int m0  = blockIdx.x * MT;

    const int g    = wid >> 2;            // K-group
    const int wq   = wid & 3;             // expert quarter
    const int lt   = lid & 7;             // token lane
    const int le   = lid >> 3;            // expert lane
    const int tokb = lt * 8;              // tokens tokb..tokb+7
    const int eb   = wq * 16 + le * 4;    // experts eb..eb+3
    const int wkey = (eb >> 2) & 7;       // w swizzle key (= (row>>2)&7, loop-inv)

    // ---- loader: 8 cp.async (16B) per thread per iteration ----
    const int lrow = tid >> 3;            // 0..31
    const int lcol = tid & 7;             // 0..7
    uint32_t xoff[2], woff[2];
    const char* xsrc[2];
    const char* wsrc[2];
    #pragma unroll
    for (int p = 0; p < 2; p++) {
        const int r = lrow + 32 * p;      // 0..63
        xoff[p] = (uint32_t)(r * 128 + ((lcol ^ ((r >> 3) & 7)) << 4));
        woff[p] = (uint32_t)(r * 128 + ((lcol ^ ((r >> 2) & 7)) << 4));
        xsrc[p] = (const char*)(x + (size_t)(m0 + r) * Hdim + lcol * 4);
        wsrc[p] = (const char*)(W + (size_t)r * Hdim + lcol * 4);
    }

    auto issue = [&](int nt) {
        const uint32_t d = (uint32_t)(nt & 1);
        #pragma unroll
        for (int gg = 0; gg < 2; gg++) {
            const uint32_t bb = sbase + (d * 2 + gg) * BUFB;
            const int kb = (gg * 2048 + nt * KT) * 4;
            #pragma unroll
            for (int p = 0; p < 2; p++)
                asm volatile("cp.async.cg.shared.global [%0], [%1], 16;"
                             :: "r"(bb + xoff[p]), "l"(xsrc[p] + kb));
            #pragma unroll
            for (int p = 0; p < 2; p++)
                asm volatile("cp.async.cg.shared.global [%0], [%1], 16;"
                             :: "r"(bb + 8192 + woff[p]), "l"(wsrc[p] + kb));
        }
        asm volatile("cp.async.commit_group;" ::: "memory");
    };

    uint64_t acc[8][4];
    #pragma unroll
    for (int i = 0; i < 8; i++)
        #pragma unroll
        for (int j = 0; j < 4; j++) acc[i][j] = 0ull;

    issue(0);

    for (int it = 0; it < ITERS; it++) {
        asm volatile("cp.async.wait_group 0;" ::: "memory");
        __syncthreads();
        if (it + 1 < ITERS) issue(it + 1);

        const uint32_t base = sbase + (uint32_t)(((it & 1) * 2 + g) * BUFB);
        const uint32_t xb = base + (uint32_t)(tokb * 128);
        const uint32_t wb = base + 8192u + (uint32_t)(eb * 128);

        #pragma unroll
        for (int q = 0; q < 8; q++) {
            uint64_t xv0[8], xv1[8];
            const uint32_t xa = xb + (uint32_t)((q ^ lt) << 4);
            #pragma unroll
            for (int i = 0; i < 8; i++)
                asm volatile("ld.shared.v2.u64 {%0,%1},[%2];"
                             : "=l"(xv0[i]), "=l"(xv1[i]) : "r"(xa + (uint32_t)(i * 128)));
            const uint32_t wa0 = wb + (uint32_t)((q ^ wkey) << 4);
            #pragma unroll
            for (int j = 0; j < 4; j++) {
                uint64_t w0, w1;
                asm volatile("ld.shared.v2.u64 {%0,%1},[%2];"
                             : "=l"(w0), "=l"(w1) : "r"(wa0 + (uint32_t)(j * 128)));
                #pragma unroll
                for (int i = 0; i < 8; i++) {
                    asm("fma.rn.f32x2 %0, %1, %2, %0;" : "+l"(acc[i][j]) : "l"(xv0[i]), "l"(w0));
                    asm("fma.rn.f32x2 %0, %1, %2, %0;" : "+l"(acc[i][j]) : "l"(xv1[i]), "l"(w1));
                }
            }
        }
    }
    __syncthreads();

    // ---- combine K-groups in smem logits [64][66] ----
    if (g == 0) {
        #pragma unroll
        for (int i = 0; i < 8; i++)
            #pragma unroll
            for (int j = 0; j < 4; j++) {
                float lo, hi;
                asm("mov.b64 {%0,%1}, %2;" : "=f"(lo), "=f"(hi) : "l"(acc[i][j]));
                smem[(tokb + i) * 66 + (eb + j)] = lo + hi;
            }
    }
    __syncthreads();
    if (g == 1) {
        #pragma unroll
        for (int i = 0; i < 8; i++)
            #pragma unroll
            for (int j = 0; j < 4; j++) {
                float lo, hi;
                asm("mov.b64 {%0,%1}, %2;" : "=f"(lo), "=f"(hi) : "l"(acc[i][j]));
                smem[(tokb + i) * 66 + (eb + j)] += lo + hi;
            }
    }
    __syncthreads();

    if (tid < MT) {
        const float* row = smem + tid * 66;
        float best1 = -3.4e38f, best2 = -3.4e38f;
        int i1 = 0, i2 = 0;
        #pragma unroll 8
        for (int e = 0; e < Edim; e++) {
            const float l = row[e];
            if (l > best1) { best2 = best1; i2 = i1; best1 = l; i1 = e; }
            else if (l > best2) { best2 = l; i2 = e; }
        }
        float Z = 0.0f;
        #pragma unroll 8
        for (int e = 0; e < Edim; e++) Z += expf(row[e] - best1);
        const float s1 = 1.0f / Z;
        const float s2 = expf(best2 - best1) / Z;
        const float p1 = 1.0f / (1.0f + expf(s2 - s1));
        const float p2 = 1.0f - p1;

        const int m = m0 + tid;
        out[2 * m + 0] = p1;
        out[2 * m + 1] = p2;
        float* oi = out + 2 * T;              // indices stored as float values
        oi[2 * m + 0] = (float)i1;
        oi[2 * m + 1] = (float)i2;
    }
    if (blockIdx.x == 0 && tid == 0) out[4 * T] = 0.0f;
}

extern "C" void kernel_launch(void* const* d_in, const int* in_sizes, int n_in,
                              void* d_out, int out_size)
{
    const float* x = (const float*)d_in[0];
    const float* W = (const float*)d_in[1];
    int T = in_sizes[0] / Hdim;   // 16384
    (void)n_in; (void)out_size;

    static bool attr_done = false;
    if (!attr_done) {
        cudaFuncSetAttribute(moe_gate_v4_kernel,
                             cudaFuncAttributeMaxDynamicSharedMemorySize, SMEM_BYTES);
        attr_done = true;
    }
    moe_gate_v4_kernel<<<T / MT, 256, SMEM_BYTES>>>(x, W, (float*)d_out, T);
}

// round 9
// speedup vs baseline: 1.0432x; 1.0432x over previous
#include <cuda_runtime.h>
#include <math.h>
#include <stdint.h>

// StableMoEGate v5.1: mma.sync.m16n8k8 TF32 with 2-way error-free split (3 passes).
// logits = x @ W^T (T=16384, H=4096, E=64); softmax; top-2; renorm softmax.
// Output: single f32 buffer [2T scores][2T idx-as-float][1 aux=0].
//
// Fix vs v5: woff K-group stride was gg*512 k8-units (whole-row); correct is gg*128.

#define Hdim 4096
#define Edim 64
#define MT   64                  // tokens per CTA
#define NCHUNK 64                // chunks per K-group (1024 k / 16)
#define SMEM_BYTES 65536         // 2 buf x 4 g x 2 k8 x 2 spl x 64 n x 32B

__device__ float g_wsplit[2 * 64 * 4096];   // [spl][n][k8(512)][8 perm]

static __device__ __forceinline__ uint32_t smem_u32(const void* p) {
    uint32_t a;
    asm("{ .reg .u64 t; cvta.to.shared.u64 t, %1; cvt.u32.u64 %0, t; }" : "=r"(a) : "l"(p));
    return a;
}
static __device__ __forceinline__ uint32_t f2tf32(float f) {
    uint32_t u;
    asm("cvt.rna.tf32.f32 %0, %1;" : "=r"(u) : "f"(f));
    return u;
}

__global__ void __launch_bounds__(256) split_w_kernel(const float* __restrict__ W) {
    const int i = blockIdx.x * 256 + threadIdx.x;
    if (i < 64 * 4096) {
        const int n = i >> 12, k = i & 4095;
        const float w = W[(size_t)n * 4096 + k];
        const uint32_t hi = f2tf32(w);
        const float hif = __uint_as_float(hi);
        const uint32_t lo = f2tf32(w - hif);
        const int k8i = k >> 3, kin = k & 7;
        const int pos = (kin & 3) * 2 + (kin >> 2);        // (k,k+4) adjacent
        const int dst = n * 4096 + k8i * 8 + pos;
        g_wsplit[dst]          = hif;
        g_wsplit[262144 + dst] = __uint_as_float(lo);
    }
}

#define MMA(d, a0, a1, a2, a3, b0, b1)                                           \
    asm volatile("mma.sync.aligned.m16n8k8.row.col.f32.tf32.tf32.f32 "           \
                 "{%0,%1,%2,%3}, {%4,%5,%6,%7}, {%8,%9}, {%0,%1,%2,%3};"         \
                 : "+f"(d[0]), "+f"(d[1]), "+f"(d[2]), "+f"(d[3])                \
                 : "r"(a0), "r"(a1), "r"(a2), "r"(a3), "r"(b0), "r"(b1))

__global__ void __launch_bounds__(256) moe_gate_v5_kernel(
    const float* __restrict__ x,
    float* __restrict__ out,
    int T)
{
    extern __shared__ float smem[];
    const uint32_t sbase = smem_u32(smem);

    const int tid  = threadIdx.x;
    const int lid  = tid & 31;
    const int wid  = tid >> 5;
    const int g    = wid >> 1;             // K-group 0..3 : k in [g*1024, g*1024+1024)
    const int tokg = wid & 1;              // token half: tokens [tokg*32, tokg*32+32)
    const int gid  = lid >> 2;             // 0..7
    const int tid4 = lid & 3;              // 0..3
    const int m0   = blockIdx.x * MT;

    // ---- cp.async source/dest precompute: 8 x 16B per thread per chunk ----
    uint32_t dstoff[8], woff[8];           // woff in bytes from g_wsplit
    #pragma unroll
    for (int j = 0; j < 8; j++) {
        const int id   = j * 256 + tid;
        const int half = id & 1;
        const int n    = (id >> 1) & 63;
        const int spl  = (id >> 7) & 1;
        const int k8   = (id >> 8) & 1;
        const int gg   = (id >> 9) & 3;
        dstoff[j] = (uint32_t)(((((gg * 2 + k8) * 2 + spl) * 64 + n) * 32) + half * 16);
        // FIX: K-group stride is 128 k8-units (1024 k), not 512
        woff[j]   = (uint32_t)((spl * 262144 + n * 4096 + (gg * 128 + k8) * 8 + half * 4) * 4);
    }
    const char* wbase = (const char*)g_wsplit;

    // ---- A pointers: byte offsets into x for the 8 fragment elements ----
    uint32_t aoff[8];
    #pragma unroll
    for (int m = 0; m < 2; m++) {
        const int r = m0 + tokg * 32 + m * 16 + gid;
        const int c = g * 1024 + tid4;
        aoff[m * 4 + 0] = (uint32_t)(((size_t)r * Hdim + c) * 4);
        aoff[m * 4 + 1] = (uint32_t)(((size_t)(r + 8) * Hdim + c) * 4);
        aoff[m * 4 + 2] = (uint32_t)(((size_t)r * Hdim + c + 4) * 4);
        aoff[m * 4 + 3] = (uint32_t)(((size_t)(r + 8) * Hdim + c + 4) * 4);
    }
    const char* xb = (const char*)x;

    float acc[2][8][4];
    #pragma unroll
    for (int m = 0; m < 2; m++)
        #pragma unroll
        for (int nt = 0; nt < 8; nt++)
            #pragma unroll
            for (int q = 0; q < 4; q++) acc[m][nt][q] = 0.0f;

    auto issue = [&](int c, uint32_t buf) {
        #pragma unroll
        for (int j = 0; j < 8; j++)
            asm volatile("cp.async.cg.shared.global [%0], [%1], 16;"
                         :: "r"(sbase + buf * 32768u + dstoff[j]),
                            "l"(wbase + woff[j] + (uint32_t)c * 64u));
        asm volatile("cp.async.commit_group;" ::: "memory");
    };

    float ar[8];
    #pragma unroll
    for (int i = 0; i < 8; i++) ar[i] = *(const float*)(xb + aoff[i]);

    issue(0, 0);

    for (int c = 0; c < NCHUNK; c++) {
        asm volatile("cp.async.wait_group 0;" ::: "memory");
        __syncthreads();
        if (c + 1 < NCHUNK) issue(c + 1, (uint32_t)((c + 1) & 1));

        #pragma unroll
        for (int k8 = 0; k8 < 2; k8++) {
            const int s = c * 2 + k8;
            float an[8];
            const uint32_t sn = (uint32_t)((s + 1 < 128 ? s + 1 : s) * 32);
            #pragma unroll
            for (int i = 0; i < 8; i++) an[i] = *(const float*)(xb + aoff[i] + sn);

            uint32_t ahi[8], alo[8];
            #pragma unroll
            for (int i = 0; i < 8; i++) {
                ahi[i] = f2tf32(ar[i]);
                alo[i] = f2tf32(ar[i] - __uint_as_float(ahi[i]));
            }

            const uint32_t b0a = sbase + (uint32_t)((c & 1) * 32768)
                               + (uint32_t)(((g * 2 + k8) * 2) * 2048)
                               + (uint32_t)(gid * 32 + tid4 * 8);
            #pragma unroll
            for (int nt = 0; nt < 8; nt++) {
                uint32_t bh0, bh1, bl0, bl1;
                asm volatile("ld.shared.v2.b32 {%0,%1},[%2];"
                             : "=r"(bh0), "=r"(bh1) : "r"(b0a + (uint32_t)(nt * 256)));
                asm volatile("ld.shared.v2.b32 {%0,%1},[%2];"
                             : "=r"(bl0), "=r"(bl1) : "r"(b0a + (uint32_t)(nt * 256) + 2048u));
                #pragma unroll
                for (int m = 0; m < 2; m++) {
                    MMA(acc[m][nt], ahi[m*4+0], ahi[m*4+1], ahi[m*4+2], ahi[m*4+3], bh0, bh1);
                    MMA(acc[m][nt], ahi[m*4+0], ahi[m*4+1], ahi[m*4+2], ahi[m*4+3], bl0, bl1);
                    MMA(acc[m][nt], alo[m*4+0], alo[m*4+1], alo[m*4+2], alo[m*4+3], bh0, bh1);
                }
            }
            #pragma unroll
            for (int i = 0; i < 8; i++) ar[i] = an[i];
        }
    }
    __syncthreads();

    // ---- split-K reduction into logits smem [64][68] ----
    #pragma unroll
    for (int gg = 0; gg < 4; gg++) {
        if (g == gg) {
            #pragma unroll
            for (int m = 0; m < 2; m++) {
                const int r = tokg * 32 + m * 16 + gid;
                #pragma unroll
                for (int nt = 0; nt < 8; nt++) {
                    const int col = nt * 8 + tid4 * 2;
                    if (gg == 0) {
                        smem[r * 68 + col]           = acc[m][nt][0];
                        smem[r * 68 + col + 1]       = acc[m][nt][1];
                        smem[(r + 8) * 68 + col]     = acc[m][nt][2];
                        smem[(r + 8) * 68 + col + 1] = acc[m][nt][3];
                    } else {
                        smem[r * 68 + col]           += acc[m][nt][0];
                        smem[r * 68 + col + 1]       += acc[m][nt][1];
                        smem[(r + 8) * 68 + col]     += acc[m][nt][2];
                        smem[(r + 8) * 68 + col + 1] += acc[m][nt][3];
                    }
                }
            }
        }
        __syncthreads();
    }

    if (tid < MT) {
        const float* row = smem + tid * 68;
        float best1 = -3.4e38f, best2 = -3.4e38f;
        int i1 = 0, i2 = 0;
        #pragma unroll 8
        for (int e = 0; e < Edim; e++) {
            const float l = row[e];
            if (l > best1) { best2 = best1; i2 = i1; best1 = l; i1 = e; }
            else if (l > best2) { best2 = l; i2 = e; }
        }
        float Z = 0.0f;
        #pragma unroll 8
        for (int e = 0; e < Edim; e++) Z += expf(row[e] - best1);
        const float s1 = 1.0f / Z;
        const float s2 = expf(best2 - best1) / Z;
        const float p1 = 1.0f / (1.0f + expf(s2 - s1));
        const float p2 = 1.0f - p1;

        const int m = m0 + tid;
        out[2 * m + 0] = p1;
        out[2 * m + 1] = p2;
        float* oi = out + 2 * T;              // indices stored as float values
        oi[2 * m + 0] = (float)i1;
        oi[2 * m + 1] = (float)i2;
    }
    if (blockIdx.x == 0 && tid == 0) out[4 * T] = 0.0f;
}

extern "C" void kernel_launch(void* const* d_in, const int* in_sizes, int n_in,
                              void* d_out, int out_size)
{
    const float* x = (const float*)d_in[0];
    const float* W = (const float*)d_in[1];
    int T = in_sizes[0] / Hdim;   // 16384
    (void)n_in; (void)out_size;

    static bool attr_done = false;
    if (!attr_done) {
        cudaFuncSetAttribute(moe_gate_v5_kernel,
                             cudaFuncAttributeMaxDynamicSharedMemorySize, SMEM_BYTES);
        attr_done = true;
    }
    split_w_kernel<<<1024, 256>>>(W);
    moe_gate_v5_kernel<<<T / MT, 256, SMEM_BYTES>>>(x, (float*)d_out, T);
}